// round 1
// baseline (speedup 1.0000x reference)
#include <cuda_runtime.h>
#include <math.h>
#include <stdint.h>

// Problem constants
#define BATCH   2
#define S_LEN   2048
#define DM      1024
#define NHEADS  16
#define HDIM    64
#define MROWS   (BATCH * S_LEN)        // 4096
#define PCOLS   (4 * DM)               // 4096
#define ATT_SCALE 0.125f               // 64^-0.5
#define LN_EPS  1e-5f

// Scratch (allocation-free rule: __device__ globals)
__device__ float g_P[(size_t)MROWS * PCOLS];   // silu(x @ W_qkuv): 4096 x 4096
__device__ float g_att[(size_t)MROWS * DM];    // gated attended:   4096 x 1024

// ---------------------------------------------------------------------------
// helpers
// ---------------------------------------------------------------------------
__device__ __forceinline__ unsigned f2tf(float x) {
    unsigned u;
    asm("cvt.rna.tf32.f32 %0, %1;" : "=r"(u) : "f"(x));
    return u;
}
__device__ __forceinline__ float4 tf4(float4 v) {
    float4 r;
    r.x = __uint_as_float(f2tf(v.x));
    r.y = __uint_as_float(f2tf(v.y));
    r.z = __uint_as_float(f2tf(v.z));
    r.w = __uint_as_float(f2tf(v.w));
    return r;
}
__device__ __forceinline__ float silu_f(float x) {
    return x / (1.0f + __expf(-x));
}
__device__ __forceinline__ void mma_tf32(float c[4], const unsigned a[4], const unsigned b[2]) {
    asm volatile(
        "mma.sync.aligned.m16n8k8.row.col.f32.tf32.tf32.f32 "
        "{%0,%1,%2,%3}, {%4,%5,%6,%7}, {%8,%9}, {%0,%1,%2,%3};\n"
        : "+f"(c[0]), "+f"(c[1]), "+f"(c[2]), "+f"(c[3])
        : "r"(a[0]), "r"(a[1]), "r"(a[2]), "r"(a[3]), "r"(b[0]), "r"(b[1]));
}

// ---------------------------------------------------------------------------
// Generic TF32 GEMM: C[M,N] = (silu?)(A[M,K] @ B[K,N]), all row-major fp32.
// CTA tile 128x128x32, 256 threads = 8 warps (4 x 2), warp tile 32x64.
// Smem pads chosen so fragment loads are bank-conflict-free (bank = 4g+t).
// ---------------------------------------------------------------------------
__global__ void __launch_bounds__(256) gemm_tf32_kernel(
    const float* __restrict__ A, const float* __restrict__ B, float* __restrict__ C,
    int M, int N, int K, int do_silu)
{
    __shared__ __align__(16) float As[128 * 36];   // [128][36]
    __shared__ __align__(16) float Bs[32 * 132];   // [32][132]

    const int tid  = threadIdx.x;
    const int warp = tid >> 5, lane = tid & 31;
    const int g = lane >> 2, t = lane & 3;
    const int m0 = blockIdx.y * 128, n0 = blockIdx.x * 128;
    const int wm = (warp >> 1) * 32, wn = (warp & 1) * 64;

    float acc[2][8][4];
#pragma unroll
    for (int mt = 0; mt < 2; mt++)
#pragma unroll
        for (int nt = 0; nt < 8; nt++)
#pragma unroll
            for (int i = 0; i < 4; i++) acc[mt][nt][i] = 0.0f;

    for (int k0 = 0; k0 < K; k0 += 32) {
        // A tile 128x32 (1024 float4, 4 per thread)
#pragma unroll
        for (int it = 0; it < 4; it++) {
            int j = tid + it * 256;
            int r = j >> 3, c4 = (j & 7) * 4;
            float4 v = *(const float4*)(A + (size_t)(m0 + r) * K + k0 + c4);
            *(float4*)&As[r * 36 + c4] = tf4(v);
        }
        // B tile 32x128
#pragma unroll
        for (int it = 0; it < 4; it++) {
            int j = tid + it * 256;
            int r = j >> 5, c4 = (j & 31) * 4;
            float4 v = *(const float4*)(B + (size_t)(k0 + r) * N + n0 + c4);
            *(float4*)&Bs[r * 132 + c4] = tf4(v);
        }
        __syncthreads();

#pragma unroll
        for (int kk = 0; kk < 4; kk++) {
            unsigned a[2][4], bb[8][2];
            const int c = kk * 8 + t;
#pragma unroll
            for (int mt = 0; mt < 2; mt++) {
                int row = wm + mt * 16 + g;
                a[mt][0] = __float_as_uint(As[row * 36 + c]);
                a[mt][1] = __float_as_uint(As[(row + 8) * 36 + c]);
                a[mt][2] = __float_as_uint(As[row * 36 + c + 4]);
                a[mt][3] = __float_as_uint(As[(row + 8) * 36 + c + 4]);
            }
#pragma unroll
            for (int nt = 0; nt < 8; nt++) {
                int col = wn + nt * 8 + g;
                bb[nt][0] = __float_as_uint(Bs[c * 132 + col]);
                bb[nt][1] = __float_as_uint(Bs[(c + 4) * 132 + col]);
            }
#pragma unroll
            for (int mt = 0; mt < 2; mt++)
#pragma unroll
                for (int nt = 0; nt < 8; nt++)
                    mma_tf32(acc[mt][nt], a[mt], bb[nt]);
        }
        __syncthreads();
    }

    // epilogue
#pragma unroll
    for (int mt = 0; mt < 2; mt++) {
        int row = m0 + wm + mt * 16 + g;
#pragma unroll
        for (int nt = 0; nt < 8; nt++) {
            int col = n0 + wn + nt * 8 + 2 * t;
            float v0 = acc[mt][nt][0], v1 = acc[mt][nt][1];
            float v2 = acc[mt][nt][2], v3 = acc[mt][nt][3];
            if (do_silu) {
                v0 = silu_f(v0); v1 = silu_f(v1); v2 = silu_f(v2); v3 = silu_f(v3);
            }
            *(float2*)(C + (size_t)row * N + col)       = make_float2(v0, v1);
            *(float2*)(C + (size_t)(row + 8) * N + col) = make_float2(v2, v3);
        }
    }
}

// ---------------------------------------------------------------------------
// Fused SiLU-attention + normalizer + LayerNorm(64) + gate.
// Grid: (S/64 q-tiles, B*H). 128 threads = 4 warps, warp owns 16 q rows.
// Streams 64-key blocks; no softmax state needed (silu attention is linear
// in the accumulation). Scores tile reuses the K smem buffer.
// ---------------------------------------------------------------------------
#define ATT_SMEM_BYTES (3 * 64 * 68 * 4)   // Qs, Ks(/Ss), Vs : 52224 bytes

__global__ void __launch_bounds__(128) attn_kernel(
    const float* __restrict__ P, const int* __restrict__ mask,
    const float* __restrict__ gamma, const float* __restrict__ beta,
    float* __restrict__ att)
{
    extern __shared__ __align__(16) float sm[];
    float* Qs = sm;                 // [64][68]
    float* Ks = sm + 64 * 68;       // [64][68], reused for S
    float* Vs = sm + 2 * 64 * 68;   // [64][68]

    const int tid = threadIdx.x, warp = tid >> 5, lane = tid & 31;
    const int g = lane >> 2, t = lane & 3;
    const int bh = blockIdx.y, b = bh >> 4, h = bh & 15;
    const int q0 = blockIdx.x * 64;

    const float* Pb    = P + (size_t)b * S_LEN * PCOLS;
    const float* qbase = Pb + h * HDIM;
    const float* kbase = Pb + DM + h * HDIM;
    const float* vbase = Pb + 2 * DM + h * HDIM;
    const float* gbase = Pb + 3 * DM + h * HDIM;
    const int*   mbase = mask + (size_t)b * S_LEN * S_LEN;

    // load Q tile (64 x 64)
#pragma unroll
    for (int it = 0; it < 8; it++) {
        int j = tid + it * 128;
        int r = j >> 4, c4 = (j & 15) * 4;
        float4 v = *(const float4*)(qbase + (size_t)(q0 + r) * PCOLS + c4);
        *(float4*)&Qs[r * 68 + c4] = tf4(v);
    }

    float o[8][4];
#pragma unroll
    for (int nt = 0; nt < 8; nt++)
#pragma unroll
        for (int i = 0; i < 4; i++) o[nt][i] = 0.0f;
    int msum0 = 0, msum1 = 0;

    const int lrow = warp * 16 + g;

    for (int kb = 0; kb < 32; kb++) {
        const int k0 = kb * 64;
        __syncthreads();   // Q visible (iter 0); prev O-mma done before K/V overwrite
        // load K and V tiles (64 x 64 each)
#pragma unroll
        for (int it = 0; it < 8; it++) {
            int j = tid + it * 128;
            int r = j >> 4, c4 = (j & 15) * 4;
            float4 kv = *(const float4*)(kbase + (size_t)(k0 + r) * PCOLS + c4);
            float4 vv = *(const float4*)(vbase + (size_t)(k0 + r) * PCOLS + c4);
            *(float4*)&Ks[r * 68 + c4] = tf4(kv);
            *(float4*)&Vs[r * 68 + c4] = tf4(vv);
        }
        __syncthreads();

        // S = Q @ K^T  (warp: 16 q-rows x 64 keys)
        float s[8][4];
#pragma unroll
        for (int nt = 0; nt < 8; nt++)
#pragma unroll
            for (int i = 0; i < 4; i++) s[nt][i] = 0.0f;

#pragma unroll
        for (int kk = 0; kk < 8; kk++) {
            const int c = kk * 8 + t;
            unsigned a[4];
            a[0] = __float_as_uint(Qs[lrow * 68 + c]);
            a[1] = __float_as_uint(Qs[(lrow + 8) * 68 + c]);
            a[2] = __float_as_uint(Qs[lrow * 68 + c + 4]);
            a[3] = __float_as_uint(Qs[(lrow + 8) * 68 + c + 4]);
#pragma unroll
            for (int nt = 0; nt < 8; nt++) {
                unsigned bb[2];
                bb[0] = __float_as_uint(Ks[(nt * 8 + g) * 68 + c]);
                bb[1] = __float_as_uint(Ks[(nt * 8 + g) * 68 + c + 4]);
                mma_tf32(s[nt], a, bb);
            }
        }
        __syncthreads();   // all warps done reading Ks before S overwrites it

        // silu * mask, mask row-sums, store S into Ks (tf32-rounded)
#pragma unroll
        for (int nt = 0; nt < 8; nt++) {
            const int lcol = nt * 8 + 2 * t;
            const int* mp0 = mbase + (size_t)(q0 + lrow) * S_LEN + k0 + lcol;
            int2 m01 = *(const int2*)mp0;
            int2 m23 = *(const int2*)(mp0 + 8 * S_LEN);
            float v0 = silu_f(s[nt][0] * ATT_SCALE) * (float)m01.x;
            float v1 = silu_f(s[nt][1] * ATT_SCALE) * (float)m01.y;
            float v2 = silu_f(s[nt][2] * ATT_SCALE) * (float)m23.x;
            float v3 = silu_f(s[nt][3] * ATT_SCALE) * (float)m23.y;
            msum0 += m01.x + m01.y;
            msum1 += m23.x + m23.y;
            *(float2*)&Ks[lrow * 68 + lcol] =
                make_float2(__uint_as_float(f2tf(v0)), __uint_as_float(f2tf(v1)));
            *(float2*)&Ks[(lrow + 8) * 68 + lcol] =
                make_float2(__uint_as_float(f2tf(v2)), __uint_as_float(f2tf(v3)));
        }
        __syncthreads();

        // O += S @ V
#pragma unroll
        for (int kk = 0; kk < 8; kk++) {
            const int c = kk * 8 + t;
            unsigned a[4];
            a[0] = __float_as_uint(Ks[lrow * 68 + c]);
            a[1] = __float_as_uint(Ks[(lrow + 8) * 68 + c]);
            a[2] = __float_as_uint(Ks[lrow * 68 + c + 4]);
            a[3] = __float_as_uint(Ks[(lrow + 8) * 68 + c + 4]);
#pragma unroll
            for (int nt = 0; nt < 8; nt++) {
                unsigned bb[2];
                bb[0] = __float_as_uint(Vs[c * 68 + nt * 8 + g]);
                bb[1] = __float_as_uint(Vs[(c + 4) * 68 + nt * 8 + g]);
                mma_tf32(o[nt], a, bb);
            }
        }
    }

    // normalizer: reduce mask sums across the 4 lanes sharing a row
    msum0 += __shfl_xor_sync(0xffffffffu, msum0, 1);
    msum0 += __shfl_xor_sync(0xffffffffu, msum0, 2);
    msum1 += __shfl_xor_sync(0xffffffffu, msum1, 1);
    msum1 += __shfl_xor_sync(0xffffffffu, msum1, 2);
    float inv0 = rsqrtf((float)(msum0 > 1 ? msum0 : 1));
    float inv1 = rsqrtf((float)(msum1 > 1 ? msum1 : 1));

    // apply normalizer, LayerNorm partial sums (64 elems per row over 4 lanes)
    float sum0 = 0.f, sq0 = 0.f, sum1 = 0.f, sq1 = 0.f;
#pragma unroll
    for (int nt = 0; nt < 8; nt++) {
        o[nt][0] *= inv0; o[nt][1] *= inv0;
        o[nt][2] *= inv1; o[nt][3] *= inv1;
        sum0 += o[nt][0] + o[nt][1];
        sq0  += o[nt][0] * o[nt][0] + o[nt][1] * o[nt][1];
        sum1 += o[nt][2] + o[nt][3];
        sq1  += o[nt][2] * o[nt][2] + o[nt][3] * o[nt][3];
    }
    sum0 += __shfl_xor_sync(0xffffffffu, sum0, 1);
    sum0 += __shfl_xor_sync(0xffffffffu, sum0, 2);
    sq0  += __shfl_xor_sync(0xffffffffu, sq0, 1);
    sq0  += __shfl_xor_sync(0xffffffffu, sq0, 2);
    sum1 += __shfl_xor_sync(0xffffffffu, sum1, 1);
    sum1 += __shfl_xor_sync(0xffffffffu, sum1, 2);
    sq1  += __shfl_xor_sync(0xffffffffu, sq1, 1);
    sq1  += __shfl_xor_sync(0xffffffffu, sq1, 2);

    const float mu0 = sum0 * (1.0f / 64.0f);
    const float mu1 = sum1 * (1.0f / 64.0f);
    const float rs0 = rsqrtf(sq0 * (1.0f / 64.0f) - mu0 * mu0 + LN_EPS);
    const float rs1 = rsqrtf(sq1 * (1.0f / 64.0f) - mu1 * mu1 + LN_EPS);

    const int grow0 = q0 + lrow, grow1 = grow0 + 8;
#pragma unroll
    for (int nt = 0; nt < 8; nt++) {
        const int d = nt * 8 + 2 * t;
        float ga0 = gamma[d], ga1 = gamma[d + 1];
        float be0 = beta[d],  be1 = beta[d + 1];
        float2 gv0 = *(const float2*)(gbase + (size_t)grow0 * PCOLS + d);
        float2 gv1 = *(const float2*)(gbase + (size_t)grow1 * PCOLS + d);
        float w0 = ((o[nt][0] - mu0) * rs0 * ga0 + be0) * gv0.x;
        float w1 = ((o[nt][1] - mu0) * rs0 * ga1 + be1) * gv0.y;
        float w2 = ((o[nt][2] - mu1) * rs1 * ga0 + be0) * gv1.x;
        float w3 = ((o[nt][3] - mu1) * rs1 * ga1 + be1) * gv1.y;
        *(float2*)(att + (size_t)(b * S_LEN + grow0) * DM + h * HDIM + d) = make_float2(w0, w1);
        *(float2*)(att + (size_t)(b * S_LEN + grow1) * DM + h * HDIM + d) = make_float2(w2, w3);
    }
}

// ---------------------------------------------------------------------------
extern "C" void kernel_launch(void* const* d_in, const int* in_sizes, int n_in,
                              void* d_out, int out_size)
{
    const float* tokens = (const float*)d_in[0];
    const int*   mask   = (const int*)d_in[1];
    const float* Wqkuv  = (const float*)d_in[2];
    const float* Wout   = (const float*)d_in[3];
    const float* gamma  = (const float*)d_in[4];
    const float* beta   = (const float*)d_in[5];
    float* out = (float*)d_out;

    float *P = nullptr, *att = nullptr;
    cudaGetSymbolAddress((void**)&P, g_P);
    cudaGetSymbolAddress((void**)&att, g_att);

    cudaFuncSetAttribute(attn_kernel, cudaFuncAttributeMaxDynamicSharedMemorySize,
                         ATT_SMEM_BYTES);

    // 1) P = silu(tokens @ W_qkuv)   [4096 x 4096]
    gemm_tf32_kernel<<<dim3(PCOLS / 128, MROWS / 128), 256>>>(
        tokens, Wqkuv, P, MROWS, PCOLS, DM, 1);

    // 2) fused attention + LN + gate -> att [4096 x 1024]
    attn_kernel<<<dim3(S_LEN / 64, BATCH * NHEADS), 128, ATT_SMEM_BYTES>>>(
        P, mask, gamma, beta, att);

    // 3) out = att @ W_out           [4096 x 1024]
    gemm_tf32_kernel<<<dim3(DM / 128, MROWS / 128), 256>>>(
        att, Wout, out, MROWS, DM, DM, 0);
}